// round 9
// baseline (speedup 1.0000x reference)
#include <cuda_runtime.h>

// Problem shapes (fixed by setup_inputs)
#define N_WORLDS 2048
#define DIM      64
#define BATCH    1024
#define MAXC     64          // max contributions per output row (actual max ~11 w.h.p.)

#define WT       256         // worlds per CTA tile
#define NTILES   (N_WORLDS / WT)   // 8
#define THREADS  512

// smem pitches (floats)
#define PW       68          // pitch for worlds + W tiles (conflict-free LDS/LDSM); 272B rows
#define PY       260         // pitch for epilogue transpose buffer (conflict-free)

// smem layout (floats). Worlds tile is only read in the prologue (A-frags are
// register-resident), so the epilogue transpose buffer sY UNIONs with it.
// W[j] is double-buffered; staged by TMA bulk copies completing on mbarriers.
#define WORLDS_OFF 0                          // [256][68] = 17408 floats
#define SY_OFF     0                          // [64][260] = 16640 floats (aliases)
#define WS_OFF     (WT * PW)                  // 17408
#define WS_BUF     (DIM * PW)                 // 4352 floats per buffer
#define MBAR_OFF_B ((WS_OFF + 2 * WS_BUF) * 4)   // 104448 (16B aligned)
#define SMEM_BYTES (MBAR_OFF_B + 16)             // 104464

#define W_TILE_BYTES (DIM * DIM * 4)          // 16384

// Scratch for row -> contribution lists (device globals: no allocation allowed)
__device__ int g_cnt[BATCH];
__device__ unsigned int g_lst[BATCH * MAXC];

// Round f32 -> tf32 (b32 destination => "=r" constraint). Idempotent.
__device__ __forceinline__ float to_tf32(float x) {
    unsigned int y;
    asm("cvt.rna.tf32.f32 %0, %1;\n" : "=r"(y) : "f"(x));
    return __uint_as_float(y);
}

__device__ __forceinline__ void mma_tf32(
    float& d0, float& d1, float& d2, float& d3,
    unsigned a0, unsigned a1, unsigned a2, unsigned a3,
    unsigned b0, unsigned b1)
{
    asm volatile(
        "mma.sync.aligned.m16n8k8.row.col.f32.tf32.tf32.f32 "
        "{%0,%1,%2,%3}, {%4,%5,%6,%7}, {%8,%9}, {%0,%1,%2,%3};\n"
        : "+f"(d0), "+f"(d1), "+f"(d2), "+f"(d3)
        : "r"(a0), "r"(a1), "r"(a2), "r"(a3), "r"(b0), "r"(b1));
}

__device__ __forceinline__ void mbar_init(unsigned mbar, unsigned count) {
    asm volatile("mbarrier.init.shared.b64 [%0], %1;\n"
                 :: "r"(mbar), "r"(count) : "memory");
}
__device__ __forceinline__ void mbar_expect_tx(unsigned mbar, unsigned bytes) {
    asm volatile("mbarrier.arrive.expect_tx.shared.b64 _, [%0], %1;\n"
                 :: "r"(mbar), "r"(bytes) : "memory");
}
__device__ __forceinline__ void mbar_wait(unsigned mbar, unsigned parity) {
    asm volatile(
        "{\n\t"
        ".reg .pred P;\n\t"
        "WAIT_%=:\n\t"
        "mbarrier.try_wait.parity.shared.b64 P, [%0], %1;\n\t"
        "@!P bra WAIT_%=;\n\t"
        "}"
        :: "r"(mbar), "r"(parity) : "memory");
}
// TMA bulk copy 256B row: global -> shared, completion on mbarrier.
__device__ __forceinline__ void tma_row(unsigned dst, const float* src, unsigned mbar) {
    asm volatile(
        "cp.async.bulk.shared::cluster.global.mbarrier::complete_tx::bytes "
        "[%0], [%1], %2, [%3];\n"
        :: "r"(dst), "l"(src), "r"(256u), "r"(mbar) : "memory");
}

// ---------------------------------------------------------------------------
// Kernel 1: bin samples by output row. Deterministic: atomic placement is
// followed by an insertion sort on the (n<<16)|j keys, so list order (and thus
// float summation order) is identical on every replay.
// ---------------------------------------------------------------------------
__global__ void bin_kernel(const int* __restrict__ nullary) {
    int tid = threadIdx.x;   // one CTA of 1024 threads
    g_cnt[tid] = 0;
    __syncthreads();

    int r = nullary[2 * tid + 0];
    int j = nullary[2 * tid + 1];
    int pos = atomicAdd(&g_cnt[r], 1);
    if (pos < MAXC)
        g_lst[r * MAXC + pos] = ((unsigned)tid << 16) | (unsigned)j;
    __syncthreads();

    int c = g_cnt[tid];
    if (c > MAXC) c = MAXC;
    unsigned* L = &g_lst[tid * MAXC];
    for (int a = 1; a < c; a++) {
        unsigned v = L[a];
        int b = a - 1;
        while (b >= 0 && L[b] > v) { L[b + 1] = L[b]; b--; }
        L[b + 1] = v;
    }
}

// ---------------------------------------------------------------------------
// Kernel 2: one CTA per (output row, 256-world tile).
// Y^T (worlds x d) = worlds_tile @ W[j]^T via mma.sync tf32:
//   A (worlds) fragments register-resident and loop-invariant,
//   B fragments via ldmatrix.x4 (b16 half-tile trick for f32 data),
//   W[j] staged by 64 TMA bulk row-copies (dst stride 272B keeps the
//     ldmatrix-conflict-free pitch) into a double buffer with mbarriers,
//   per-sample L2 norm over d via quad shfl reduction (no smem),
//   one smem transpose at the end, coalesced streaming float4 stores.
// Zero-count rows take a pure zero-fill fast path.
// ---------------------------------------------------------------------------
extern __shared__ float smem[];

__global__ void __launch_bounds__(THREADS, 1)
nullary_kernel(const float* __restrict__ worlds,
               const float* __restrict__ W,
               float* __restrict__ out) {
    const int tid  = threadIdx.x;
    const int warp = tid >> 5;
    const int lane = tid & 31;
    const int g    = lane >> 2;   // groupID (0..7)
    const int tg   = lane & 3;    // thread-in-group (0..3)

    const int r  = blockIdx.y;
    const int w0 = blockIdx.x * WT;
    float* outp = out + (size_t)r * (DIM * N_WORLDS) + w0;

    int c = g_cnt[r];
    if (c > MAXC) c = MAXC;

    if (c == 0) {
        // zero-fill fast path: 64 rows x 256 cols, float4, coalesced, streaming
        float4 z = make_float4(0.f, 0.f, 0.f, 0.f);
        #pragma unroll
        for (int i = tid; i < DIM * WT / 4; i += THREADS) {
            int d = i >> 6, q = i & 63;
            __stcs((float4*)(outp + (size_t)d * N_WORLDS + q * 4), z);
        }
        return;
    }

    float* sWor = smem + WORLDS_OFF;
    float* sY   = smem + SY_OFF;
    const unsigned sbase = (unsigned)__cvta_generic_to_shared(smem);
    const unsigned mbar0 = sbase + MBAR_OFF_B;
    const unsigned mbar1 = mbar0 + 8;
    const unsigned* lst  = &g_lst[r * MAXC];

    if (tid == 0) { mbar_init(mbar0, 1); mbar_init(mbar1, 1); }
    __syncthreads();   // mbarrier init visible to warp 0's expect_tx/TMA

    // Prefetch W[j0] into buffer 0 via TMA bulk rows (warp 0 issues).
    if (warp == 0) {
        if (lane == 0) mbar_expect_tx(mbar0, W_TILE_BYTES);
        __syncwarp();
        const int j0 = (int)(lst[0] & 0xFFFFu);
        const float* src = W + (size_t)j0 * (DIM * DIM);
        const unsigned dbase = sbase + (unsigned)(WS_OFF * 4);
        tma_row(dbase + (unsigned)(lane * PW * 4),        src + lane * DIM,        mbar0);
        tma_row(dbase + (unsigned)((lane + 32) * PW * 4), src + (lane + 32) * DIM, mbar0);
    }

    // Prologue: stage worlds tile (tf32-rounded) [w][e], pitch PW
    {
        const float4* gw = (const float4*)(worlds + (size_t)w0 * DIM);
        #pragma unroll
        for (int i = tid; i < WT * (DIM / 4); i += THREADS) {
            int w = i >> 4, e4 = i & 15;
            float4 v = __ldg(&gw[i]);
            v.x = to_tf32(v.x); v.y = to_tf32(v.y);
            v.z = to_tf32(v.z); v.w = to_tf32(v.w);
            *(float4*)&sWor[w * PW + e4 * 4] = v;
        }
    }
    __syncthreads();   // worlds tile visible

    // A fragments (worlds rows), loop-invariant, register-resident.
    // m16n8k8 A map: a0(row=g,col=tg) a1(row=g+8,col=tg) a2(row=g,col=tg+4) a3(row=g+8,col=tg+4)
    unsigned A0[8], A1[8], A2[8], A3[8];
    {
        const int row0 = (warp * 16 + g) * PW;
        const int row1 = (warp * 16 + 8 + g) * PW;
        #pragma unroll
        for (int ks = 0; ks < 8; ks++) {
            A0[ks] = __float_as_uint(sWor[row0 + tg     + 8 * ks]);
            A2[ks] = __float_as_uint(sWor[row0 + tg + 4 + 8 * ks]);
            A1[ks] = __float_as_uint(sWor[row1 + tg     + 8 * ks]);
            A3[ks] = __float_as_uint(sWor[row1 + tg + 4 + 8 * ks]);
        }
    }

    float ACC[32];
    #pragma unroll
    for (int k = 0; k < 32; k++) ACC[k] = 0.f;

    // ldmatrix lane-constant address part (4 sub-groups of 8 lanes):
    //   sub=0: b0 of ks even (+0B)  sub=1: b1 of ks even (+16B)
    //   sub=2: b0 of ks odd (+32B)  sub=3: b1 of ks odd (+48B)
    const int lrow = lane & 7;
    const int sub  = lane >> 3;
    const unsigned lane_off = (unsigned)(((sub & 1) * 16) + ((sub >> 1) * 32)
                                         + lrow * PW * 4);

    unsigned ph0 = 0, ph1 = 0;   // per-buffer mbarrier phase parity

    for (int ci = 0; ci < c; ci++) {
        __syncthreads();   // all warps done reading buf[(ci+1)&1] (iter ci-1)

        if (warp == 0 && ci + 1 < c) {
            const unsigned mb = ((ci + 1) & 1) ? mbar1 : mbar0;
            if (lane == 0) mbar_expect_tx(mb, W_TILE_BYTES);
            __syncwarp();
            const int jn = (int)(lst[ci + 1] & 0xFFFFu);
            const float* src = W + (size_t)jn * (DIM * DIM);
            const unsigned dbase = sbase
                + (unsigned)((WS_OFF + ((ci + 1) & 1) * WS_BUF) * 4);
            tma_row(dbase + (unsigned)(lane * PW * 4),        src + lane * DIM,        mb);
            tma_row(dbase + (unsigned)((lane + 32) * PW * 4), src + (lane + 32) * DIM, mb);
        }

        // Wait for buf[ci&1]
        if (ci & 1) { mbar_wait(mbar1, ph1); ph1 ^= 1; }
        else        { mbar_wait(mbar0, ph0); ph0 ^= 1; }

        const unsigned wbase = sbase
            + (unsigned)((WS_OFF + (ci & 1) * WS_BUF) * 4) + lane_off;

        // Y^T[16w x 64d] per warp, fully in registers.
        float Y[32];
        #pragma unroll
        for (int k = 0; k < 32; k++) Y[k] = 0.f;

        #pragma unroll
        for (int nt = 0; nt < 8; nt++) {
            const unsigned abase = wbase + (unsigned)(nt * 8 * PW * 4);
            #pragma unroll
            for (int kp = 0; kp < 4; kp++) {
                unsigned b00, b01, b10, b11;   // (b0,b1) for ks=2kp and ks=2kp+1
                asm volatile(
                    "ldmatrix.sync.aligned.m8n8.x4.shared.b16 {%0,%1,%2,%3}, [%4];\n"
                    : "=r"(b00), "=r"(b01), "=r"(b10), "=r"(b11)
                    : "r"(abase + (unsigned)(kp * 64)));
                mma_tf32(Y[4*nt], Y[4*nt+1], Y[4*nt+2], Y[4*nt+3],
                         A0[2*kp],   A1[2*kp],   A2[2*kp],   A3[2*kp],   b00, b01);
                mma_tf32(Y[4*nt], Y[4*nt+1], Y[4*nt+2], Y[4*nt+3],
                         A0[2*kp+1], A1[2*kp+1], A2[2*kp+1], A3[2*kp+1], b10, b11);
            }
        }

        // Per-world L2 norm over d (= n dimension; quad holds the full row).
        float s0 = 0.f, s1 = 0.f;
        #pragma unroll
        for (int nt = 0; nt < 8; nt++) {
            s0 += Y[4*nt]   * Y[4*nt]   + Y[4*nt+1] * Y[4*nt+1];
            s1 += Y[4*nt+2] * Y[4*nt+2] + Y[4*nt+3] * Y[4*nt+3];
        }
        s0 += __shfl_xor_sync(0xFFFFFFFFu, s0, 1);
        s0 += __shfl_xor_sync(0xFFFFFFFFu, s0, 2);
        s1 += __shfl_xor_sync(0xFFFFFFFFu, s1, 1);
        s1 += __shfl_xor_sync(0xFFFFFFFFu, s1, 2);
        const float sc0 = rsqrtf(fmaxf(s0, 1e-12f));
        const float sc1 = rsqrtf(fmaxf(s1, 1e-12f));

        #pragma unroll
        for (int nt = 0; nt < 8; nt++) {
            ACC[4*nt]   += Y[4*nt]   * sc0;
            ACC[4*nt+1] += Y[4*nt+1] * sc0;
            ACC[4*nt+2] += Y[4*nt+2] * sc1;
            ACC[4*nt+3] += Y[4*nt+3] * sc1;
        }
    }

    // Epilogue: transpose ACC (w-major frags) -> sY [d][w], then coalesced
    // streaming stores. sY aliases the worlds tile (dead after A-frag load).
    __syncthreads();   // close reads of sWor (aliased by sY)
    #pragma unroll
    for (int nt = 0; nt < 8; nt++) {
        const int d0 = nt * 8 + 2 * tg;
        const int wl = warp * 16 + g;
        sY[d0       * PY + wl]     = ACC[4*nt];
        sY[(d0 + 1) * PY + wl]     = ACC[4*nt+1];
        sY[d0       * PY + wl + 8] = ACC[4*nt+2];
        sY[(d0 + 1) * PY + wl + 8] = ACC[4*nt+3];
    }
    __syncthreads();

    #pragma unroll
    for (int k4 = 0; k4 < 8; k4++) {
        int idx4 = tid + THREADS * k4;
        int d = idx4 >> 6, q = idx4 & 63;
        float4 v = *(float4*)&sY[d * PY + q * 4];
        __stcs((float4*)(outp + (size_t)d * N_WORLDS + q * 4), v);
    }
}

// ---------------------------------------------------------------------------
extern "C" void kernel_launch(void* const* d_in, const int* in_sizes, int n_in,
                              void* d_out, int out_size) {
    (void)in_sizes; (void)n_in; (void)out_size;
    const float* worlds  = (const float*)d_in[0];   // (2048, 64) f32
    const float* W       = (const float*)d_in[1];   // (512, 64, 64) f32
    const int*   nullary = (const int*)d_in[2];     // (1024, 2) i32
    float*       out     = (float*)d_out;           // (1024, 64, 2048) f32

    cudaFuncSetAttribute(nullary_kernel,
                         cudaFuncAttributeMaxDynamicSharedMemorySize,
                         SMEM_BYTES);

    bin_kernel<<<1, BATCH>>>(nullary);
    nullary_kernel<<<dim3(NTILES, BATCH), THREADS, SMEM_BYTES>>>(worlds, W, out);
}

// round 10
// speedup vs baseline: 1.0828x; 1.0828x over previous
#include <cuda_runtime.h>

// Problem shapes (fixed by setup_inputs)
#define N_WORLDS 2048
#define DIM      64
#define BATCH    1024
#define MAXC     64          // max contributions per output row (actual max ~11 w.h.p.)

#define WT       128         // worlds per CTA tile
#define NTILES   (N_WORLDS / WT)   // 16
#define THREADS  256
#define RPC      8           // rows per CTA
#define NROWG    (BATCH / RPC)     // 128 row groups

// smem pitches (floats)
#define PW       68          // pitch for worlds + W tiles (conflict-free LDS/LDSM); 272B rows
#define PY       132         // pitch for epilogue transpose buffer

// smem layout (floats)
#define WORLDS_OFF 0                          // [128][68] = 8704
#define WS_OFF     (WT * PW)                  // 8704; 2 x [64][68] = 8704
#define WS_BUF     (DIM * PW)                 // 4352 per buffer
#define SY_OFF     (WS_OFF + 2 * WS_BUF)      // 17408; [64][132] = 8448
#define FLAT_OFF   (SY_OFF + DIM * PY)        // 25856; 512 uints (8*MAXC)
#define META_OFF   (FLAT_OFF + RPC * MAXC)    // 26368; [0]=m, [1..8]=counts
#define MBAR_OFF_F (META_OFF + 16)            // 26384 -> byte 105536, 16B aligned
#define SMEM_BYTES ((MBAR_OFF_F + 4) * 4)     // 105552

#define W_TILE_BYTES (DIM * DIM * 4)          // 16384

// Scratch for row -> contribution lists (device globals: no allocation allowed)
__device__ int g_cnt[BATCH];
__device__ unsigned int g_lst[BATCH * MAXC];

// Round f32 -> tf32 (b32 destination => "=r" constraint). Idempotent.
__device__ __forceinline__ float to_tf32(float x) {
    unsigned int y;
    asm("cvt.rna.tf32.f32 %0, %1;\n" : "=r"(y) : "f"(x));
    return __uint_as_float(y);
}

__device__ __forceinline__ void mma_tf32(
    float& d0, float& d1, float& d2, float& d3,
    unsigned a0, unsigned a1, unsigned a2, unsigned a3,
    unsigned b0, unsigned b1)
{
    asm volatile(
        "mma.sync.aligned.m16n8k8.row.col.f32.tf32.tf32.f32 "
        "{%0,%1,%2,%3}, {%4,%5,%6,%7}, {%8,%9}, {%0,%1,%2,%3};\n"
        : "+f"(d0), "+f"(d1), "+f"(d2), "+f"(d3)
        : "r"(a0), "r"(a1), "r"(a2), "r"(a3), "r"(b0), "r"(b1));
}

__device__ __forceinline__ void mbar_init(unsigned mbar, unsigned count) {
    asm volatile("mbarrier.init.shared.b64 [%0], %1;\n"
                 :: "r"(mbar), "r"(count) : "memory");
}
__device__ __forceinline__ void mbar_expect_tx(unsigned mbar, unsigned bytes) {
    asm volatile("mbarrier.arrive.expect_tx.shared.b64 _, [%0], %1;\n"
                 :: "r"(mbar), "r"(bytes) : "memory");
}
__device__ __forceinline__ void mbar_wait(unsigned mbar, unsigned parity) {
    asm volatile(
        "{\n\t"
        ".reg .pred P;\n\t"
        "WAIT_%=:\n\t"
        "mbarrier.try_wait.parity.shared.b64 P, [%0], %1;\n\t"
        "@!P bra WAIT_%=;\n\t"
        "}"
        :: "r"(mbar), "r"(parity) : "memory");
}
// TMA bulk copy 256B row: global -> shared, completion on mbarrier.
__device__ __forceinline__ void tma_row(unsigned dst, const float* src, unsigned mbar) {
    asm volatile(
        "cp.async.bulk.shared::cluster.global.mbarrier::complete_tx::bytes "
        "[%0], [%1], %2, [%3];\n"
        :: "r"(dst), "l"(src), "r"(256u), "r"(mbar) : "memory");
}

// ---------------------------------------------------------------------------
// Kernel 1: bin samples by output row (deterministic order via sort).
// ---------------------------------------------------------------------------
__global__ void bin_kernel(const int* __restrict__ nullary) {
    int tid = threadIdx.x;   // one CTA of 1024 threads
    g_cnt[tid] = 0;
    __syncthreads();

    int r = nullary[2 * tid + 0];
    int j = nullary[2 * tid + 1];
    int pos = atomicAdd(&g_cnt[r], 1);
    if (pos < MAXC)
        g_lst[r * MAXC + pos] = ((unsigned)tid << 16) | (unsigned)j;
    __syncthreads();

    int c = g_cnt[tid];
    if (c > MAXC) c = MAXC;
    unsigned* L = &g_lst[tid * MAXC];
    for (int a = 1; a < c; a++) {
        unsigned v = L[a];
        int b = a - 1;
        while (b >= 0 && L[b] > v) { L[b + 1] = L[b]; b--; }
        L[b + 1] = v;
    }
}

// ---------------------------------------------------------------------------
// Kernel 2: one CTA per (8-row group, 128-world tile).
//   Worlds A-frags loaded ONCE per CTA (amortized over 8 rows).
//   Flattened contribution list over the 8 rows; TMA double-buffered W staging
//   pipelines across row boundaries. Row flush: quad-shfl L2 norm done per
//   contribution; ACC transposed via smem, streaming float4 stores.
//   Zero-count rows: fire-and-forget zero stores before the main loop.
// ---------------------------------------------------------------------------
extern __shared__ float smem[];

__global__ void __launch_bounds__(THREADS, 2)
nullary_kernel(const float* __restrict__ worlds,
               const float* __restrict__ W,
               float* __restrict__ out) {
    const int tid  = threadIdx.x;
    const int warp = tid >> 5;
    const int lane = tid & 31;
    const int g    = lane >> 2;   // groupID (0..7)
    const int tg   = lane & 3;    // thread-in-group (0..3)

    const int r0 = blockIdx.y * RPC;
    const int w0 = blockIdx.x * WT;

    float*    sWor  = smem + WORLDS_OFF;
    float*    sY    = smem + SY_OFF;
    unsigned* sFlat = (unsigned*)(smem + FLAT_OFF);
    unsigned* sMeta = (unsigned*)(smem + META_OFF);
    const unsigned sbase = (unsigned)__cvta_generic_to_shared(smem);
    const unsigned mbar0 = sbase + MBAR_OFF_F * 4;
    const unsigned mbar1 = mbar0 + 8;

    // Stage worlds tile (tf32-rounded) [w][e], pitch PW — once per CTA.
    {
        const float4* gw = (const float4*)(worlds + (size_t)w0 * DIM);
        #pragma unroll
        for (int i = tid; i < WT * (DIM / 4); i += THREADS) {
            int w = i >> 4, e4 = i & 15;
            float4 v = __ldg(&gw[i]);
            v.x = to_tf32(v.x); v.y = to_tf32(v.y);
            v.z = to_tf32(v.z); v.w = to_tf32(v.w);
            *(float4*)&sWor[w * PW + e4 * 4] = v;
        }
    }

    // Thread 0: mbarriers + flattened (row, j) list for the 8 rows.
    if (tid == 0) {
        mbar_init(mbar0, 1);
        mbar_init(mbar1, 1);
        int m = 0;
        for (int rl = 0; rl < RPC; rl++) {
            int cc = g_cnt[r0 + rl];
            if (cc > MAXC) cc = MAXC;
            sMeta[1 + rl] = (unsigned)cc;
            for (int k = 0; k < cc; k++)
                sFlat[m++] = ((unsigned)rl << 24)
                           | (g_lst[(r0 + rl) * MAXC + k] & 0xFFFFu);
        }
        sMeta[0] = (unsigned)m;
    }
    __syncthreads();   // worlds, flat list, mbarriers visible

    const int m = (int)sMeta[0];

    // Prefetch W for flat[0] into buffer 0 (warp 0; 64 TMA bulk rows).
    if (warp == 0 && m > 0) {
        if (lane == 0) mbar_expect_tx(mbar0, W_TILE_BYTES);
        __syncwarp();
        const int j0 = (int)(sFlat[0] & 0xFFFFu);
        const float* src = W + (size_t)j0 * (DIM * DIM);
        const unsigned dbase = sbase + (unsigned)(WS_OFF * 4);
        tma_row(dbase + (unsigned)(lane * PW * 4),        src + lane * DIM,        mbar0);
        tma_row(dbase + (unsigned)((lane + 32) * PW * 4), src + (lane + 32) * DIM, mbar0);
    }

    // Zero-fill stores for empty rows (overlaps the first TMA latency).
    {
        float4 z = make_float4(0.f, 0.f, 0.f, 0.f);
        for (int rl = 0; rl < RPC; rl++) {
            if (sMeta[1 + rl] == 0) {
                float* outp = out + (size_t)(r0 + rl) * (DIM * N_WORLDS) + w0;
                #pragma unroll
                for (int i = tid; i < DIM * WT / 4; i += THREADS) {
                    int d = i >> 5, q = i & 31;
                    __stcs((float4*)(outp + (size_t)d * N_WORLDS + q * 4), z);
                }
            }
        }
    }
    if (m == 0) return;

    // A fragments (worlds rows), loop-invariant, register-resident.
    unsigned A0[8], A1[8], A2[8], A3[8];
    {
        const int row0 = (warp * 16 + g) * PW;
        const int row1 = (warp * 16 + 8 + g) * PW;
        #pragma unroll
        for (int ks = 0; ks < 8; ks++) {
            A0[ks] = __float_as_uint(sWor[row0 + tg     + 8 * ks]);
            A2[ks] = __float_as_uint(sWor[row0 + tg + 4 + 8 * ks]);
            A1[ks] = __float_as_uint(sWor[row1 + tg     + 8 * ks]);
            A3[ks] = __float_as_uint(sWor[row1 + tg + 4 + 8 * ks]);
        }
    }

    float ACC[32];
    #pragma unroll
    for (int k = 0; k < 32; k++) ACC[k] = 0.f;

    // ldmatrix lane-constant address part (4 sub-groups of 8 lanes).
    const int lrow = lane & 7;
    const int sub  = lane >> 3;
    const unsigned lane_off = (unsigned)(((sub & 1) * 16) + ((sub >> 1) * 32)
                                         + lrow * PW * 4);

    unsigned ph0 = 0, ph1 = 0;

    for (int i = 0; i < m; i++) {
        __syncthreads();   // all warps done with iter i-1 (buf reads + sY reads)

        if (warp == 0 && i + 1 < m) {
            const unsigned mb = ((i + 1) & 1) ? mbar1 : mbar0;
            if (lane == 0) mbar_expect_tx(mb, W_TILE_BYTES);
            __syncwarp();
            const int jn = (int)(sFlat[i + 1] & 0xFFFFu);
            const float* src = W + (size_t)jn * (DIM * DIM);
            const unsigned dbase = sbase
                + (unsigned)((WS_OFF + ((i + 1) & 1) * WS_BUF) * 4);
            tma_row(dbase + (unsigned)(lane * PW * 4),        src + lane * DIM,        mb);
            tma_row(dbase + (unsigned)((lane + 32) * PW * 4), src + (lane + 32) * DIM, mb);
        }

        if (i & 1) { mbar_wait(mbar1, ph1); ph1 ^= 1; }
        else       { mbar_wait(mbar0, ph0); ph0 ^= 1; }

        const unsigned wbase = sbase
            + (unsigned)((WS_OFF + (i & 1) * WS_BUF) * 4) + lane_off;

        // Y^T[16w x 64d] per warp, fully in registers.
        float Y[32];
        #pragma unroll
        for (int k = 0; k < 32; k++) Y[k] = 0.f;

        #pragma unroll
        for (int nt = 0; nt < 8; nt++) {
            const unsigned abase = wbase + (unsigned)(nt * 8 * PW * 4);
            #pragma unroll
            for (int kp = 0; kp < 4; kp++) {
                unsigned b00, b01, b10, b11;
                asm volatile(
                    "ldmatrix.sync.aligned.m8n8.x4.shared.b16 {%0,%1,%2,%3}, [%4];\n"
                    : "=r"(b00), "=r"(b01), "=r"(b10), "=r"(b11)
                    : "r"(abase + (unsigned)(kp * 64)));
                mma_tf32(Y[4*nt], Y[4*nt+1], Y[4*nt+2], Y[4*nt+3],
                         A0[2*kp],   A1[2*kp],   A2[2*kp],   A3[2*kp],   b00, b01);
                mma_tf32(Y[4*nt], Y[4*nt+1], Y[4*nt+2], Y[4*nt+3],
                         A0[2*kp+1], A1[2*kp+1], A2[2*kp+1], A3[2*kp+1], b10, b11);
            }
        }

        // Per-world L2 norm over d (quad holds the full row).
        float s0 = 0.f, s1 = 0.f;
        #pragma unroll
        for (int nt = 0; nt < 8; nt++) {
            s0 += Y[4*nt]   * Y[4*nt]   + Y[4*nt+1] * Y[4*nt+1];
            s1 += Y[4*nt+2] * Y[4*nt+2] + Y[4*nt+3] * Y[4*nt+3];
        }
        s0 += __shfl_xor_sync(0xFFFFFFFFu, s0, 1);
        s0 += __shfl_xor_sync(0xFFFFFFFFu, s0, 2);
        s1 += __shfl_xor_sync(0xFFFFFFFFu, s1, 1);
        s1 += __shfl_xor_sync(0xFFFFFFFFu, s1, 2);
        const float sc0 = rsqrtf(fmaxf(s0, 1e-12f));
        const float sc1 = rsqrtf(fmaxf(s1, 1e-12f));

        #pragma unroll
        for (int nt = 0; nt < 8; nt++) {
            ACC[4*nt]   += Y[4*nt]   * sc0;
            ACC[4*nt+1] += Y[4*nt+1] * sc0;
            ACC[4*nt+2] += Y[4*nt+2] * sc1;
            ACC[4*nt+3] += Y[4*nt+3] * sc1;
        }

        // Row flush: last contribution of this row -> transpose + store.
        const int rl = (int)(sFlat[i] >> 24);
        const bool flush = (i + 1 == m) || ((int)(sFlat[i + 1] >> 24) != rl);
        if (flush) {
            #pragma unroll
            for (int nt = 0; nt < 8; nt++) {
                const int d0 = nt * 8 + 2 * tg;
                const int wl = warp * 16 + g;
                sY[d0       * PY + wl]     = ACC[4*nt];
                sY[(d0 + 1) * PY + wl]     = ACC[4*nt+1];
                sY[d0       * PY + wl + 8] = ACC[4*nt+2];
                sY[(d0 + 1) * PY + wl + 8] = ACC[4*nt+3];
            }
            __syncthreads();   // sY fully written

            float* outp = out + (size_t)(r0 + rl) * (DIM * N_WORLDS) + w0;
            #pragma unroll
            for (int k4 = 0; k4 < 8; k4++) {
                int idx4 = tid + THREADS * k4;
                int d = idx4 >> 5, q = idx4 & 31;
                float4 v = *(float4*)&sY[d * PY + q * 4];
                __stcs((float4*)(outp + (size_t)d * N_WORLDS + q * 4), v);
            }
            #pragma unroll
            for (int k = 0; k < 32; k++) ACC[k] = 0.f;
            // next iteration's top __syncthreads closes sY reads before reuse
        }
    }
}

// ---------------------------------------------------------------------------
extern "C" void kernel_launch(void* const* d_in, const int* in_sizes, int n_in,
                              void* d_out, int out_size) {
    (void)in_sizes; (void)n_in; (void)out_size;
    const float* worlds  = (const float*)d_in[0];   // (2048, 64) f32
    const float* W       = (const float*)d_in[1];   // (512, 64, 64) f32
    const int*   nullary = (const int*)d_in[2];     // (1024, 2) i32
    float*       out     = (float*)d_out;           // (1024, 64, 2048) f32

    cudaFuncSetAttribute(nullary_kernel,
                         cudaFuncAttributeMaxDynamicSharedMemorySize,
                         SMEM_BYTES);

    bin_kernel<<<1, BATCH>>>(nullary);
    nullary_kernel<<<dim3(NTILES, NROWG), THREADS, SMEM_BYTES>>>(worlds, W, out);
}

// round 11
// speedup vs baseline: 1.4989x; 1.3843x over previous
#include <cuda_runtime.h>

// Problem shapes (fixed by setup_inputs)
#define N_WORLDS 2048
#define DIM      64
#define BATCH    1024
#define MAXC     64          // max contributions per output row (actual max ~11 w.h.p.)

#define WT       128         // worlds per CTA tile
#define NTILES   (N_WORLDS / WT)   // 16
#define THREADS  256

// smem pitches (floats)
#define PW       68          // pitch for W tiles (conflict-free LDSM); 272B rows
#define PY       132         // pitch for epilogue transpose buffer

// smem layout (floats): W double buffer + epilogue transpose buffer.
#define WS_OFF     0
#define WS_BUF     (DIM * PW)                 // 4352 per buffer
#define SY_OFF     (2 * WS_BUF)               // 8704; [64][132] = 8448
#define SMEM_FLOATS (SY_OFF + DIM * PY)       // 17152
#define SMEM_BYTES  (SMEM_FLOATS * 4)         // 68608

// Device-global scratch (no allocation allowed)
__device__ int g_cnt[BATCH];
__device__ unsigned int g_lst[BATCH * MAXC];
// Precomputed A-fragments: [tile][warp][ks][lane] -> float4 (A0,A1,A2,A3),
// tf32-rounded. 16*8*8*32*4 floats = 512 KB.
__device__ float4 g_A[NTILES * 8 * 8 * 32];

// Round f32 -> tf32 (b32 destination => "=r" constraint). Idempotent.
__device__ __forceinline__ float to_tf32(float x) {
    unsigned int y;
    asm("cvt.rna.tf32.f32 %0, %1;\n" : "=r"(y) : "f"(x));
    return __uint_as_float(y);
}

__device__ __forceinline__ void mma_tf32(
    float& d0, float& d1, float& d2, float& d3,
    unsigned a0, unsigned a1, unsigned a2, unsigned a3,
    unsigned b0, unsigned b1)
{
    asm volatile(
        "mma.sync.aligned.m16n8k8.row.col.f32.tf32.tf32.f32 "
        "{%0,%1,%2,%3}, {%4,%5,%6,%7}, {%8,%9}, {%0,%1,%2,%3};\n"
        : "+f"(d0), "+f"(d1), "+f"(d2), "+f"(d3)
        : "r"(a0), "r"(a1), "r"(a2), "r"(a3), "r"(b0), "r"(b1));
}

// ---------------------------------------------------------------------------
// Kernel 1: bin samples by output row (deterministic order via sort).
// ---------------------------------------------------------------------------
__global__ void bin_kernel(const int* __restrict__ nullary) {
    int tid = threadIdx.x;   // one CTA of 1024 threads
    g_cnt[tid] = 0;
    __syncthreads();

    int r = nullary[2 * tid + 0];
    int j = nullary[2 * tid + 1];
    int pos = atomicAdd(&g_cnt[r], 1);
    if (pos < MAXC)
        g_lst[r * MAXC + pos] = ((unsigned)tid << 16) | (unsigned)j;
    __syncthreads();

    int c = g_cnt[tid];
    if (c > MAXC) c = MAXC;
    unsigned* L = &g_lst[tid * MAXC];
    for (int a = 1; a < c; a++) {
        unsigned v = L[a];
        int b = a - 1;
        while (b >= 0 && L[b] > v) { L[b + 1] = L[b]; b--; }
        L[b + 1] = v;
    }
}

// ---------------------------------------------------------------------------
// Kernel 1b: precompute A-fragments (worlds, tf32-rounded) in the exact
// register layout each (tile, warp, lane) needs, so the main kernel's
// prologue is 8 coalesced LDG.128 with no staging, no sync, no LDS.
// m16n8k8 A map for warp slot w of tile t, lane (g,tg):
//   A0[ks]=worlds[t*128+w*16+g  ][tg  +8ks]  A1[ks]=worlds[...+8+g][tg  +8ks]
//   A2[ks]=worlds[t*128+w*16+g  ][tg+4+8ks]  A3[ks]=worlds[...+8+g][tg+4+8ks]
// ---------------------------------------------------------------------------
__global__ void prep_a_kernel(const float* __restrict__ worlds) {
    const int t    = blockIdx.x;        // tile 0..15
    const int tid  = threadIdx.x;       // 256
    const int w    = tid >> 5;
    const int lane = tid & 31;
    const int g    = lane >> 2;
    const int tg   = lane & 3;

    const float* r0 = worlds + (size_t)(t * WT + w * 16 + g)     * DIM;
    const float* r1 = worlds + (size_t)(t * WT + w * 16 + 8 + g) * DIM;
    float4* dst = g_A + ((t * 8 + w) * 8) * 32 + lane;

    #pragma unroll
    for (int ks = 0; ks < 8; ks++) {
        float4 v;
        v.x = to_tf32(r0[tg     + 8 * ks]);
        v.y = to_tf32(r1[tg     + 8 * ks]);
        v.z = to_tf32(r0[tg + 4 + 8 * ks]);
        v.w = to_tf32(r1[tg + 4 + 8 * ks]);
        dst[ks * 32] = v;
    }
}

// ---------------------------------------------------------------------------
// Kernel 2: one CTA per (output row, 128-world tile). R7 structure with the
// worlds prologue replaced by coalesced A-frag LDG from g_A.
// ---------------------------------------------------------------------------
extern __shared__ float smem[];

__global__ void __launch_bounds__(THREADS, 2)
nullary_kernel(const float* __restrict__ W,
               float* __restrict__ out) {
    const int tid  = threadIdx.x;
    const int warp = tid >> 5;
    const int lane = tid & 31;
    const int g    = lane >> 2;
    const int tg   = lane & 3;

    const int r  = blockIdx.y;
    const int w0 = blockIdx.x * WT;
    float* outp = out + (size_t)r * (DIM * N_WORLDS) + w0;

    int c = g_cnt[r];
    if (c > MAXC) c = MAXC;

    if (c == 0) {
        float4 z = make_float4(0.f, 0.f, 0.f, 0.f);
        #pragma unroll
        for (int i = tid; i < DIM * WT / 4; i += THREADS) {
            int d = i >> 5, q = i & 31;
            __stcs((float4*)(outp + (size_t)d * N_WORLDS + q * 4), z);
        }
        return;
    }

    float* sY = smem + SY_OFF;
    const unsigned sbase = (unsigned)__cvta_generic_to_shared(smem);
    const unsigned* lst = &g_lst[r * MAXC];

    // Prefetch W[j0] into buffer 0 with cp.async.cg (16B chunks).
    {
        const int j0 = (int)(lst[0] & 0xFFFFu);
        const float4* src = (const float4*)(W + (size_t)j0 * (DIM * DIM));
        const unsigned dbase = sbase + (unsigned)(WS_OFF * 4);
        #pragma unroll
        for (int k = 0; k < 4; k++) {
            int i = tid + THREADS * k;
            unsigned dst = dbase + (unsigned)(((i >> 4) * PW + (i & 15) * 4) * 4);
            asm volatile("cp.async.cg.shared.global [%0], [%1], 16;\n"
                         :: "r"(dst), "l"(src + i) : "memory");
        }
        asm volatile("cp.async.commit_group;\n" ::: "memory");
    }

    // A fragments: 8 coalesced L2-hot LDG.128, no staging, no sync.
    unsigned A0[8], A1[8], A2[8], A3[8];
    {
        const float4* ga = g_A + ((blockIdx.x * 8 + warp) * 8) * 32 + lane;
        #pragma unroll
        for (int ks = 0; ks < 8; ks++) {
            float4 v = __ldg(&ga[ks * 32]);
            A0[ks] = __float_as_uint(v.x);
            A1[ks] = __float_as_uint(v.y);
            A2[ks] = __float_as_uint(v.z);
            A3[ks] = __float_as_uint(v.w);
        }
    }

    float ACC[32];
    #pragma unroll
    for (int k = 0; k < 32; k++) ACC[k] = 0.f;

    // ldmatrix lane-constant address part (4 sub-groups of 8 lanes):
    //   sub=0: b0 of ks even (+0B)  sub=1: b1 of ks even (+16B)
    //   sub=2: b0 of ks odd (+32B)  sub=3: b1 of ks odd (+48B)
    const int lrow = lane & 7;
    const int sub  = lane >> 3;
    const unsigned lane_off = (unsigned)(((sub & 1) * 16) + ((sub >> 1) * 32)
                                         + lrow * PW * 4);

    for (int ci = 0; ci < c; ci++) {
        asm volatile("cp.async.wait_group 0;\n" ::: "memory");
        __syncthreads();   // buf[ci&1] ready; prior reads of buf[(ci+1)&1] closed

        if (ci + 1 < c) {
            const int jn = (int)(lst[ci + 1] & 0xFFFFu);
            const float4* src = (const float4*)(W + (size_t)jn * (DIM * DIM));
            const unsigned dbase = sbase
                + (unsigned)((WS_OFF + ((ci + 1) & 1) * WS_BUF) * 4);
            #pragma unroll
            for (int k = 0; k < 4; k++) {
                int i = tid + THREADS * k;
                unsigned dst = dbase + (unsigned)(((i >> 4) * PW + (i & 15) * 4) * 4);
                asm volatile("cp.async.cg.shared.global [%0], [%1], 16;\n"
                             :: "r"(dst), "l"(src + i) : "memory");
            }
            asm volatile("cp.async.commit_group;\n" ::: "memory");
        }

        const unsigned wbase = sbase
            + (unsigned)((WS_OFF + (ci & 1) * WS_BUF) * 4) + lane_off;

        // Y^T[16w x 64d] per warp, fully in registers.
        float Y[32];
        #pragma unroll
        for (int k = 0; k < 32; k++) Y[k] = 0.f;

        #pragma unroll
        for (int nt = 0; nt < 8; nt++) {
            const unsigned abase = wbase + (unsigned)(nt * 8 * PW * 4);
            #pragma unroll
            for (int kp = 0; kp < 4; kp++) {
                unsigned b00, b01, b10, b11;   // (b0,b1) for ks=2kp and 2kp+1
                asm volatile(
                    "ldmatrix.sync.aligned.m8n8.x4.shared.b16 {%0,%1,%2,%3}, [%4];\n"
                    : "=r"(b00), "=r"(b01), "=r"(b10), "=r"(b11)
                    : "r"(abase + (unsigned)(kp * 64)));
                mma_tf32(Y[4*nt], Y[4*nt+1], Y[4*nt+2], Y[4*nt+3],
                         A0[2*kp],   A1[2*kp],   A2[2*kp],   A3[2*kp],   b00, b01);
                mma_tf32(Y[4*nt], Y[4*nt+1], Y[4*nt+2], Y[4*nt+3],
                         A0[2*kp+1], A1[2*kp+1], A2[2*kp+1], A3[2*kp+1], b10, b11);
            }
        }

        // Per-world L2 norm over d (quad holds the full row).
        float s0 = 0.f, s1 = 0.f;
        #pragma unroll
        for (int nt = 0; nt < 8; nt++) {
            s0 += Y[4*nt]   * Y[4*nt]   + Y[4*nt+1] * Y[4*nt+1];
            s1 += Y[4*nt+2] * Y[4*nt+2] + Y[4*nt+3] * Y[4*nt+3];
        }
        s0 += __shfl_xor_sync(0xFFFFFFFFu, s0, 1);
        s0 += __shfl_xor_sync(0xFFFFFFFFu, s0, 2);
        s1 += __shfl_xor_sync(0xFFFFFFFFu, s1, 1);
        s1 += __shfl_xor_sync(0xFFFFFFFFu, s1, 2);
        const float sc0 = rsqrtf(fmaxf(s0, 1e-12f));
        const float sc1 = rsqrtf(fmaxf(s1, 1e-12f));

        #pragma unroll
        for (int nt = 0; nt < 8; nt++) {
            ACC[4*nt]   += Y[4*nt]   * sc0;
            ACC[4*nt+1] += Y[4*nt+1] * sc0;
            ACC[4*nt+2] += Y[4*nt+2] * sc1;
            ACC[4*nt+3] += Y[4*nt+3] * sc1;
        }
    }

    // Epilogue: transpose ACC (w-major frags) -> sY [d][w] (own smem region;
    // per-warp columns are disjoint), then coalesced streaming stores.
    #pragma unroll
    for (int nt = 0; nt < 8; nt++) {
        const int d0 = nt * 8 + 2 * tg;
        const int wl = warp * 16 + g;
        sY[d0       * PY + wl]     = ACC[4*nt];
        sY[(d0 + 1) * PY + wl]     = ACC[4*nt+1];
        sY[d0       * PY + wl + 8] = ACC[4*nt+2];
        sY[(d0 + 1) * PY + wl + 8] = ACC[4*nt+3];
    }
    __syncthreads();

    #pragma unroll
    for (int k4 = 0; k4 < 8; k4++) {
        int idx4 = tid + THREADS * k4;
        int d = idx4 >> 5, q = idx4 & 31;
        float4 v = *(float4*)&sY[d * PY + q * 4];
        __stcs((float4*)(outp + (size_t)d * N_WORLDS + q * 4), v);
    }
}

// ---------------------------------------------------------------------------
extern "C" void kernel_launch(void* const* d_in, const int* in_sizes, int n_in,
                              void* d_out, int out_size) {
    (void)in_sizes; (void)n_in; (void)out_size;
    const float* worlds  = (const float*)d_in[0];   // (2048, 64) f32
    const float* W       = (const float*)d_in[1];   // (512, 64, 64) f32
    const int*   nullary = (const int*)d_in[2];     // (1024, 2) i32
    float*       out     = (float*)d_out;           // (1024, 64, 2048) f32

    cudaFuncSetAttribute(nullary_kernel,
                         cudaFuncAttributeMaxDynamicSharedMemorySize,
                         SMEM_BYTES);

    prep_a_kernel<<<NTILES, THREADS>>>(worlds);
    bin_kernel<<<1, BATCH>>>(nullary);
    nullary_kernel<<<dim3(NTILES, BATCH), THREADS, SMEM_BYTES>>>(W, out);
}